// round 1
// baseline (speedup 1.0000x reference)
#include <cuda_runtime.h>
#include <math.h>
#include <stdint.h>

#define NMAX 100000
#define EMAX 1600000
#define DD 64

// ---------------- device scratch (no allocations allowed) ----------------
__device__ int   g_counts[NMAX];
__device__ int   g_fill[NMAX];
__device__ int   g_rowptr[NMAX + 1];
__device__ int   g_esrc[EMAX];
__device__ float g_y[(size_t)NMAX * DD];
__device__ float g_agg[(size_t)NMAX * DD];
__device__ float g_M1[DD * DD];
__device__ float g_M2[DD * DD];
__device__ float g_v[DD];
__device__ float g_bias;
__device__ int   g_is64;

// ---------------- dtype detection for edges (int64 vs int32) -------------
__global__ void detect_kernel(const void* __restrict__ edges) {
    __shared__ int nz;
    if (threadIdx.x == 0) nz = 0;
    __syncthreads();
    const int* w = (const int*)edges;
    int local = 0;
    // If edges are int64 (values < 2^31), every odd int32 word is 0.
    for (int i = threadIdx.x; i < 2048; i += blockDim.x)
        if (w[2 * i + 1] != 0) local = 1;
    if (local) atomicOr(&nz, 1);
    __syncthreads();
    if (threadIdx.x == 0) g_is64 = (nz == 0) ? 1 : 0;
}

__global__ void zero_kernel(int n) {
    int i = blockIdx.x * blockDim.x + threadIdx.x;
    if (i < n) g_counts[i] = 0;
}

__global__ void hist_kernel(const void* __restrict__ edges, int E) {
    int e = blockIdx.x * blockDim.x + threadIdx.x;
    if (e >= E) return;
    int dst;
    if (g_is64) dst = (int)((const long long*)edges)[E + e];
    else        dst = ((const int*)edges)[E + e];
    atomicAdd(&g_counts[dst], 1);
}

// single-block exclusive scan over counts -> rowptr (+ copy to fill)
__global__ void scan_kernel(int N) {
    __shared__ int ssum[1024];
    int t = threadIdx.x;
    int chunk = (N + 1023) >> 10;
    int base = t * chunk;
    int end = base + chunk; if (end > N) end = N;
    int s = 0;
    for (int i = base; i < end; i++) s += g_counts[i];
    ssum[t] = s;
    __syncthreads();
    for (int off = 1; off < 1024; off <<= 1) {
        int v = (t >= off) ? ssum[t - off] : 0;
        __syncthreads();
        ssum[t] += v;
        __syncthreads();
    }
    int run = (t == 0) ? 0 : ssum[t - 1];
    for (int i = base; i < end; i++) {
        g_rowptr[i] = run;
        g_fill[i] = run;
        run += g_counts[i];
    }
    if (t == 1023) g_rowptr[N] = ssum[1023];
}

__global__ void scatter_kernel(const void* __restrict__ edges, int E) {
    int e = blockIdx.x * blockDim.x + threadIdx.x;
    if (e >= E) return;
    int src, dst;
    if (g_is64) {
        const long long* p = (const long long*)edges;
        src = (int)p[e]; dst = (int)p[E + e];
    } else {
        const int* p = (const int*)edges;
        src = p[e]; dst = p[E + e];
    }
    int pos = atomicAdd(&g_fill[dst], 1);
    g_esrc[pos] = src;
}

// fold weights: M1 = Wp1*Wt0, M2 = Wp2*Wt1, v = Wout*Wt2, bias
__global__ void matprep_kernel(const float* __restrict__ Wp,
                               const float* __restrict__ Wt,
                               const float* __restrict__ Wout,
                               const float* __restrict__ bout) {
    int t = blockIdx.x * blockDim.x + threadIdx.x;
    if (t >= DD * DD) return;
    int i = t >> 6, k = t & 63;
    float s1 = 0.f, s2 = 0.f;
#pragma unroll
    for (int m = 0; m < DD; m++) {
        s1 += Wp[1 * DD * DD + i * DD + m] * Wt[0 * DD * DD + m * DD + k];
        s2 += Wp[2 * DD * DD + i * DD + m] * Wt[1 * DD * DD + m * DD + k];
    }
    g_M1[t] = s1;
    g_M2[t] = s2;
    if (i == 0) {
        float sv = 0.f;
#pragma unroll
        for (int m = 0; m < DD; m++)
            sv += Wout[m] * Wt[2 * DD * DD + m * DD + k];
        g_v[k] = sv;
    }
    if (t == 0) g_bias = bout[0];
}

// out[n] = in[n] @ M^T    (M row-major [64][64]); 16 nodes per block.
// Thread owns output column j (M row in registers); x row broadcast from SMEM.
__global__ void __launch_bounds__(256, 6)
gemm_kernel(const float* __restrict__ x, const float* __restrict__ M,
            float* __restrict__ out, int N) {
    __shared__ float sx[16][DD];
    int t = threadIdx.x;
    int j = t & 63;
    int g0 = t >> 6;        // 0..3
    float Mreg[DD];
#pragma unroll
    for (int k = 0; k < DD; k += 4) {
        float4 m4 = *(const float4*)&M[j * DD + k];
        Mreg[k] = m4.x; Mreg[k + 1] = m4.y; Mreg[k + 2] = m4.z; Mreg[k + 3] = m4.w;
    }
    int base = blockIdx.x * 16;
    int rows = N - base; if (rows > 16) rows = 16;
    // load tile: 16 rows * 64 floats = 256 float4
    {
        int nfloats = rows * DD;
        int off = t * 4;
        if (off + 3 < nfloats) {
            float4 v = *(const float4*)&x[(size_t)base * DD + off];
            *(float4*)&sx[0][off & ~3] = v;  // off is already 4-aligned
        } else {
            for (int q = 0; q < 4; q++)
                if (off + q < nfloats)
                    sx[0][off + q] = x[(size_t)base * DD + off + q];
        }
    }
    __syncthreads();
#pragma unroll
    for (int g = 0; g < 16; g += 4) {
        int gg = g + g0;
        if (base + gg >= N) break;
        float acc = 0.f;
#pragma unroll
        for (int k = 0; k < DD; k++) acc += Mreg[k] * sx[gg][k];
        out[(size_t)(base + gg) * DD + j] = acc;
    }
}

// agg[i] = max_{src in N(i)} y[src] - y[i]  (0 for isolated nodes). Warp/node.
__global__ void agg_kernel(const float* __restrict__ y,
                           float* __restrict__ out, int N) {
    int wid = (blockIdx.x * blockDim.x + threadIdx.x) >> 5;
    int lane = threadIdx.x & 31;
    if (wid >= N) return;
    int beg = g_rowptr[wid];
    int end = g_rowptr[wid + 1];
    float mx = -INFINITY, my = -INFINITY;
    int e = beg;
    for (; e + 1 < end; e += 2) {
        int j0 = g_esrc[e];
        int j1 = g_esrc[e + 1];
        float2 v0 = *(const float2*)&y[(size_t)j0 * DD + lane * 2];
        float2 v1 = *(const float2*)&y[(size_t)j1 * DD + lane * 2];
        mx = fmaxf(mx, fmaxf(v0.x, v1.x));
        my = fmaxf(my, fmaxf(v0.y, v1.y));
    }
    if (e < end) {
        int j0 = g_esrc[e];
        float2 v0 = *(const float2*)&y[(size_t)j0 * DD + lane * 2];
        mx = fmaxf(mx, v0.x);
        my = fmaxf(my, v0.y);
    }
    float2 o;
    if (beg == end) {
        o.x = 0.f; o.y = 0.f;
    } else {
        float2 self = *(const float2*)&y[(size_t)wid * DD + lane * 2];
        o.x = mx - self.x;
        o.y = my - self.y;
    }
    *(float2*)&out[(size_t)wid * DD + lane * 2] = o;
}

// score[i] = sigmoid(dot(agg[i], v) + b). Warp/node, shuffle reduce.
__global__ void final_kernel(const float* __restrict__ agg,
                             float* __restrict__ out, int N) {
    int wid = (blockIdx.x * blockDim.x + threadIdx.x) >> 5;
    int lane = threadIdx.x & 31;
    if (wid >= N) return;
    float2 a = *(const float2*)&agg[(size_t)wid * DD + lane * 2];
    float2 vv = *(const float2*)&g_v[lane * 2];
    float p = a.x * vv.x + a.y * vv.y;
#pragma unroll
    for (int off = 16; off; off >>= 1)
        p += __shfl_xor_sync(0xffffffffu, p, off);
    if (lane == 0) {
        float s = p + g_bias;
        out[wid] = 1.f / (1.f + expf(-s));
    }
}

extern "C" void kernel_launch(void* const* d_in, const int* in_sizes, int n_in,
                              void* d_out, int out_size) {
    const float* x    = (const float*)d_in[0];
    const void*  edges = d_in[1];
    const float* Wp   = (const float*)d_in[2];
    const float* Wt   = (const float*)d_in[3];
    const float* Wout = (const float*)d_in[4];
    const float* bout = (const float*)d_in[5];
    float* out = (float*)d_out;

    int N = in_sizes[0] / DD;
    int E = in_sizes[1] / 2;

    float *yp, *aggp, *m1p, *m2p;
    cudaGetSymbolAddress((void**)&yp, g_y);
    cudaGetSymbolAddress((void**)&aggp, g_agg);
    cudaGetSymbolAddress((void**)&m1p, g_M1);
    cudaGetSymbolAddress((void**)&m2p, g_M2);

    const int TB = 256;
    int ebl = (E + TB - 1) / TB;
    int nbl = (N + TB - 1) / TB;
    int wbl = ((N * 32) + TB - 1) / TB;   // warp-per-node grids
    int gbl = (N + 15) / 16;

    detect_kernel<<<1, 256>>>(edges);
    zero_kernel<<<nbl, TB>>>(N);
    hist_kernel<<<ebl, TB>>>(edges, E);
    scan_kernel<<<1, 1024>>>(N);
    scatter_kernel<<<ebl, TB>>>(edges, E);
    matprep_kernel<<<16, 256>>>(Wp, Wt, Wout, bout);

    // layer 0: y = x @ Wp0^T
    gemm_kernel<<<gbl, 256>>>(x, Wp, yp, N);
    agg_kernel<<<wbl, TB>>>(yp, aggp, N);
    // layer 1: y = agg @ (Wp1 Wt0)^T
    gemm_kernel<<<gbl, 256>>>(aggp, m1p, yp, N);
    agg_kernel<<<wbl, TB>>>(yp, aggp, N);
    // layer 2: y = agg @ (Wp2 Wt1)^T
    gemm_kernel<<<gbl, 256>>>(aggp, m2p, yp, N);
    agg_kernel<<<wbl, TB>>>(yp, aggp, N);
    // head: sigmoid(agg @ (Wout Wt2)^T + b)
    final_kernel<<<wbl, TB>>>(aggp, out, N);
}

// round 2
// speedup vs baseline: 1.2273x; 1.2273x over previous
#include <cuda_runtime.h>
#include <math.h>
#include <stdint.h>

#define NMAX 100000
#define EMAX 1600000
#define DD 64
#define SCAN_B 256        // scan grid blocks (256*512 = 131072 >= NMAX)

// ---------------- device scratch (no allocations allowed) ----------------
__device__ int   g_counts[NMAX];
__device__ int   g_fill[NMAX];
__device__ int   g_rowptr[NMAX + 1];
__device__ int   g_esrc[EMAX];
__device__ int   g_blocksums[SCAN_B];
__device__ int   g_blockoff[SCAN_B];
__device__ float g_y[(size_t)NMAX * DD];
__device__ float g_agg[(size_t)NMAX * DD];
__device__ float g_M1[DD * DD];
__device__ float g_M2[DD * DD];
__device__ float g_v[DD];
__device__ float g_bias;
__device__ int   g_is64;

// ---------------- dtype detection for edges (int64 vs int32) -------------
__global__ void detect_kernel(const void* __restrict__ edges) {
    __shared__ int nz;
    if (threadIdx.x == 0) nz = 0;
    __syncthreads();
    const int* w = (const int*)edges;
    int local = 0;
    // If edges are int64 (values < 2^31), every odd int32 word is 0.
    for (int i = threadIdx.x; i < 2048; i += blockDim.x)
        if (w[2 * i + 1] != 0) local = 1;
    if (local) atomicOr(&nz, 1);
    __syncthreads();
    if (threadIdx.x == 0) g_is64 = (nz == 0) ? 1 : 0;
}

__global__ void zero_kernel(int n) {
    int i = blockIdx.x * blockDim.x + threadIdx.x;
    if (i < n) g_counts[i] = 0;
}

__global__ void hist_kernel(const void* __restrict__ edges, int E) {
    int e = blockIdx.x * blockDim.x + threadIdx.x;
    if (e >= E) return;
    int dst;
    if (g_is64) dst = (int)((const long long*)edges)[E + e];
    else        dst = ((const int*)edges)[E + e];
    atomicAdd(&g_counts[dst], 1);
}

// ---------------- 3-phase parallel exclusive scan -------------------------
// Phase 1: per-block sums (256 blocks x 256 threads x 2 elements)
__global__ void scan_p1(int N) {
    __shared__ int sm[256];
    int b = blockIdx.x, t = threadIdx.x;
    int base = b * 512 + t * 2;
    int s = 0;
    if (base < N)     s += g_counts[base];
    if (base + 1 < N) s += g_counts[base + 1];
    sm[t] = s;
    __syncthreads();
    for (int off = 128; off; off >>= 1) {
        if (t < off) sm[t] += sm[t + off];
        __syncthreads();
    }
    if (t == 0) g_blocksums[b] = sm[0];
}

// Phase 2: single block exclusive-scans the 256 block sums
__global__ void scan_p2(int N) {
    __shared__ int sm[SCAN_B];
    int t = threadIdx.x;
    int orig = g_blocksums[t];
    sm[t] = orig;
    __syncthreads();
    for (int off = 1; off < SCAN_B; off <<= 1) {
        int v = (t >= off) ? sm[t - off] : 0;
        __syncthreads();
        sm[t] += v;
        __syncthreads();
    }
    g_blockoff[t] = sm[t] - orig;     // exclusive
    if (t == SCAN_B - 1) g_rowptr[N] = sm[t];   // total
}

// Phase 3: each block rescans its chunk with global offset, writes rowptr+fill
__global__ void scan_p3(int N) {
    __shared__ int sm[256];
    int b = blockIdx.x, t = threadIdx.x;
    int base = b * 512 + t * 2;
    int c0 = (base < N) ? g_counts[base] : 0;
    int c1 = (base + 1 < N) ? g_counts[base + 1] : 0;
    int s = c0 + c1;
    sm[t] = s;
    __syncthreads();
    for (int off = 1; off < 256; off <<= 1) {
        int v = (t >= off) ? sm[t - off] : 0;
        __syncthreads();
        sm[t] += v;
        __syncthreads();
    }
    int pre = sm[t] - s + g_blockoff[b];
    if (base < N)     { g_rowptr[base] = pre;          g_fill[base] = pre; }
    if (base + 1 < N) { g_rowptr[base + 1] = pre + c0; g_fill[base + 1] = pre + c0; }
}

__global__ void scatter_kernel(const void* __restrict__ edges, int E) {
    int e = blockIdx.x * blockDim.x + threadIdx.x;
    if (e >= E) return;
    int src, dst;
    if (g_is64) {
        const long long* p = (const long long*)edges;
        src = (int)p[e]; dst = (int)p[E + e];
    } else {
        const int* p = (const int*)edges;
        src = p[e]; dst = p[E + e];
    }
    int pos = atomicAdd(&g_fill[dst], 1);
    g_esrc[pos] = src;
}

// fold weights: M1 = Wp1*Wt0, M2 = Wp2*Wt1, v = Wout*Wt2, bias
__global__ void matprep_kernel(const float* __restrict__ Wp,
                               const float* __restrict__ Wt,
                               const float* __restrict__ Wout,
                               const float* __restrict__ bout) {
    int t = blockIdx.x * blockDim.x + threadIdx.x;
    if (t >= DD * DD) return;
    int i = t >> 6, k = t & 63;
    float s1 = 0.f, s2 = 0.f;
#pragma unroll
    for (int m = 0; m < DD; m++) {
        s1 += Wp[1 * DD * DD + i * DD + m] * Wt[0 * DD * DD + m * DD + k];
        s2 += Wp[2 * DD * DD + i * DD + m] * Wt[1 * DD * DD + m * DD + k];
    }
    g_M1[t] = s1;
    g_M2[t] = s2;
    if (i == 0) {
        float sv = 0.f;
#pragma unroll
        for (int m = 0; m < DD; m++)
            sv += Wout[m] * Wt[2 * DD * DD + m * DD + k];
        g_v[k] = sv;
    }
    if (t == 0) g_bias = bout[0];
}

// out[n] = in[n] @ M^T    (M row-major [64][64]); 16 nodes per block.
__global__ void __launch_bounds__(256, 6)
gemm_kernel(const float* __restrict__ x, const float* __restrict__ M,
            float* __restrict__ out, int N) {
    __shared__ float sx[16][DD];
    int t = threadIdx.x;
    int j = t & 63;
    int g0 = t >> 6;        // 0..3
    float Mreg[DD];
#pragma unroll
    for (int k = 0; k < DD; k += 4) {
        float4 m4 = *(const float4*)&M[j * DD + k];
        Mreg[k] = m4.x; Mreg[k + 1] = m4.y; Mreg[k + 2] = m4.z; Mreg[k + 3] = m4.w;
    }
    int base = blockIdx.x * 16;
    int rows = N - base; if (rows > 16) rows = 16;
    {
        int nfloats = rows * DD;
        int off = t * 4;
        if (off + 3 < nfloats) {
            float4 v = *(const float4*)&x[(size_t)base * DD + off];
            *(float4*)&sx[0][off] = v;
        } else {
            for (int q = 0; q < 4; q++)
                if (off + q < nfloats)
                    sx[0][off + q] = x[(size_t)base * DD + off + q];
        }
    }
    __syncthreads();
#pragma unroll
    for (int g = 0; g < 16; g += 4) {
        int gg = g + g0;
        if (base + gg >= N) break;
        float acc = 0.f;
#pragma unroll
        for (int k = 0; k < DD; k++) acc += Mreg[k] * sx[gg][k];
        out[(size_t)(base + gg) * DD + j] = acc;
    }
}

__device__ __forceinline__ float4 max4(float4 a, float4 b) {
    float4 r;
    r.x = fmaxf(a.x, b.x); r.y = fmaxf(a.y, b.y);
    r.z = fmaxf(a.z, b.z); r.w = fmaxf(a.w, b.w);
    return r;
}

// agg[i] = max_{src in N(i)} y[src] - y[i]  (0 for isolated nodes).
// Warp/node; lanes 0-15 handle even edges, 16-31 odd edges; float4 per lane.
__global__ void agg_kernel(const float* __restrict__ y,
                           float* __restrict__ out, int N) {
    int wid = (blockIdx.x * blockDim.x + threadIdx.x) >> 5;
    int lane = threadIdx.x & 31;
    if (wid >= N) return;
    int beg = g_rowptr[wid];
    int end = g_rowptr[wid + 1];
    int half = lane >> 4;
    int q = lane & 15;
    float4 m = make_float4(-INFINITY, -INFINITY, -INFINITY, -INFINITY);
    for (int e = beg + half; e < end; e += 2) {
        int j = g_esrc[e];
        float4 v = *(const float4*)&y[(size_t)j * DD + q * 4];
        m = max4(m, v);
    }
    // fold odd-half into even-half (and vice versa — all lanes end identical per q)
    m.x = fmaxf(m.x, __shfl_xor_sync(0xffffffffu, m.x, 16));
    m.y = fmaxf(m.y, __shfl_xor_sync(0xffffffffu, m.y, 16));
    m.z = fmaxf(m.z, __shfl_xor_sync(0xffffffffu, m.z, 16));
    m.w = fmaxf(m.w, __shfl_xor_sync(0xffffffffu, m.w, 16));
    if (lane < 16) {
        float4 o;
        if (beg == end) {
            o = make_float4(0.f, 0.f, 0.f, 0.f);
        } else {
            float4 self = *(const float4*)&y[(size_t)wid * DD + q * 4];
            o.x = m.x - self.x; o.y = m.y - self.y;
            o.z = m.z - self.z; o.w = m.w - self.w;
        }
        *(float4*)&out[(size_t)wid * DD + q * 4] = o;
    }
}

// last layer: agg + dot with folded head vector + sigmoid, fused.
__global__ void agg_final_kernel(const float* __restrict__ y,
                                 float* __restrict__ out, int N) {
    int wid = (blockIdx.x * blockDim.x + threadIdx.x) >> 5;
    int lane = threadIdx.x & 31;
    if (wid >= N) return;
    int beg = g_rowptr[wid];
    int end = g_rowptr[wid + 1];
    int half = lane >> 4;
    int q = lane & 15;
    float4 m = make_float4(-INFINITY, -INFINITY, -INFINITY, -INFINITY);
    for (int e = beg + half; e < end; e += 2) {
        int j = g_esrc[e];
        float4 v = *(const float4*)&y[(size_t)j * DD + q * 4];
        m = max4(m, v);
    }
    m.x = fmaxf(m.x, __shfl_xor_sync(0xffffffffu, m.x, 16));
    m.y = fmaxf(m.y, __shfl_xor_sync(0xffffffffu, m.y, 16));
    m.z = fmaxf(m.z, __shfl_xor_sync(0xffffffffu, m.z, 16));
    m.w = fmaxf(m.w, __shfl_xor_sync(0xffffffffu, m.w, 16));
    float p = 0.f;
    if (beg != end) {
        float4 self = *(const float4*)&y[(size_t)wid * DD + q * 4];
        float4 vv = *(const float4*)&g_v[q * 4];
        p = (m.x - self.x) * vv.x + (m.y - self.y) * vv.y
          + (m.z - self.z) * vv.z + (m.w - self.w) * vv.w;
    }
    // lanes 16-31 mirror lanes 0-15 (same q, same folded m, same self/v),
    // so reduce only over offsets 8,4,2,1 on the lower 16 lanes' values.
#pragma unroll
    for (int off = 8; off; off >>= 1)
        p += __shfl_xor_sync(0xffffffffu, p, off);
    if (lane == 0)
        out[wid] = 1.f / (1.f + expf(-(p + g_bias)));
}

extern "C" void kernel_launch(void* const* d_in, const int* in_sizes, int n_in,
                              void* d_out, int out_size) {
    const float* x     = (const float*)d_in[0];
    const void*  edges = d_in[1];
    const float* Wp    = (const float*)d_in[2];
    const float* Wt    = (const float*)d_in[3];
    const float* Wout  = (const float*)d_in[4];
    const float* bout  = (const float*)d_in[5];
    float* out = (float*)d_out;

    int N = in_sizes[0] / DD;
    int E = in_sizes[1] / 2;

    float *yp, *aggp, *m1p, *m2p;
    cudaGetSymbolAddress((void**)&yp, g_y);
    cudaGetSymbolAddress((void**)&aggp, g_agg);
    cudaGetSymbolAddress((void**)&m1p, g_M1);
    cudaGetSymbolAddress((void**)&m2p, g_M2);

    const int TB = 256;
    int ebl = (E + TB - 1) / TB;
    int nbl = (N + TB - 1) / TB;
    int wbl = ((N * 32) + TB - 1) / TB;   // warp-per-node grids
    int gbl = (N + 15) / 16;

    detect_kernel<<<1, 256>>>(edges);
    zero_kernel<<<nbl, TB>>>(N);
    hist_kernel<<<ebl, TB>>>(edges, E);
    scan_p1<<<SCAN_B, 256>>>(N);
    scan_p2<<<1, SCAN_B>>>(N);
    scan_p3<<<SCAN_B, 256>>>(N);
    scatter_kernel<<<ebl, TB>>>(edges, E);
    matprep_kernel<<<16, 256>>>(Wp, Wt, Wout, bout);

    // layer 0: y = x @ Wp0^T
    gemm_kernel<<<gbl, 256>>>(x, Wp, yp, N);
    agg_kernel<<<wbl, TB>>>(yp, aggp, N);
    // layer 1: y = agg @ (Wp1 Wt0)^T
    gemm_kernel<<<gbl, 256>>>(aggp, m1p, yp, N);
    agg_kernel<<<wbl, TB>>>(yp, aggp, N);
    // layer 2: y = agg @ (Wp2 Wt1)^T, head fused into aggregation
    gemm_kernel<<<gbl, 256>>>(aggp, m2p, yp, N);
    agg_final_kernel<<<wbl, TB>>>(yp, out, N);
}

// round 3
// speedup vs baseline: 2.9932x; 2.4390x over previous
#include <cuda_runtime.h>
#include <math.h>
#include <stdint.h>

#define NMAX 100000
#define EMAX 1600000
#define DD 64
#define SCAN_B 256        // scan grid blocks (256*512 = 131072 >= NMAX)

// ---------------- device scratch (no allocations allowed) ----------------
__device__ int   g_counts[NMAX];
__device__ int   g_fill[NMAX];
__device__ int   g_rowptr[NMAX + 1];
__device__ int   g_esrc[EMAX];
__device__ int   g_blocksums[SCAN_B];
__device__ int   g_blockoff[SCAN_B];
__device__ float g_y[(size_t)NMAX * DD];
__device__ float g_agg[(size_t)NMAX * DD];
__device__ float g_M1[DD * DD];
__device__ float g_M2[DD * DD];
__device__ float g_v[DD];
__device__ float g_bias;
__device__ int   g_is64;

// ---------------- dtype detection for edges (int64 vs int32) -------------
__global__ void detect_kernel(const void* __restrict__ edges) {
    __shared__ int nz;
    if (threadIdx.x == 0) nz = 0;
    __syncthreads();
    const int* w = (const int*)edges;
    int local = 0;
    for (int i = threadIdx.x; i < 2048; i += blockDim.x)
        if (w[2 * i + 1] != 0) local = 1;
    if (local) atomicOr(&nz, 1);
    __syncthreads();
    if (threadIdx.x == 0) g_is64 = (nz == 0) ? 1 : 0;
}

__global__ void zero_kernel(int n) {
    int i = blockIdx.x * blockDim.x + threadIdx.x;
    if (i < n) g_counts[i] = 0;
}

__global__ void hist_kernel(const void* __restrict__ edges, int E) {
    int e = blockIdx.x * blockDim.x + threadIdx.x;
    if (e >= E) return;
    int dst;
    if (g_is64) dst = (int)((const long long*)edges)[E + e];
    else        dst = ((const int*)edges)[E + e];
    atomicAdd(&g_counts[dst], 1);
}

// ---------------- 3-phase parallel exclusive scan -------------------------
__global__ void scan_p1(int N) {
    __shared__ int sm[256];
    int b = blockIdx.x, t = threadIdx.x;
    int base = b * 512 + t * 2;
    int s = 0;
    if (base < N)     s += g_counts[base];
    if (base + 1 < N) s += g_counts[base + 1];
    sm[t] = s;
    __syncthreads();
    for (int off = 128; off; off >>= 1) {
        if (t < off) sm[t] += sm[t + off];
        __syncthreads();
    }
    if (t == 0) g_blocksums[b] = sm[0];
}

__global__ void scan_p2(int N) {
    __shared__ int sm[SCAN_B];
    int t = threadIdx.x;
    int orig = g_blocksums[t];
    sm[t] = orig;
    __syncthreads();
    for (int off = 1; off < SCAN_B; off <<= 1) {
        int v = (t >= off) ? sm[t - off] : 0;
        __syncthreads();
        sm[t] += v;
        __syncthreads();
    }
    g_blockoff[t] = sm[t] - orig;
    if (t == SCAN_B - 1) g_rowptr[N] = sm[t];
}

__global__ void scan_p3(int N) {
    __shared__ int sm[256];
    int b = blockIdx.x, t = threadIdx.x;
    int base = b * 512 + t * 2;
    int c0 = (base < N) ? g_counts[base] : 0;
    int c1 = (base + 1 < N) ? g_counts[base + 1] : 0;
    int s = c0 + c1;
    sm[t] = s;
    __syncthreads();
    for (int off = 1; off < 256; off <<= 1) {
        int v = (t >= off) ? sm[t - off] : 0;
        __syncthreads();
        sm[t] += v;
        __syncthreads();
    }
    int pre = sm[t] - s + g_blockoff[b];
    if (base < N)     { g_rowptr[base] = pre;          g_fill[base] = pre; }
    if (base + 1 < N) { g_rowptr[base + 1] = pre + c0; g_fill[base + 1] = pre + c0; }
}

__global__ void scatter_kernel(const void* __restrict__ edges, int E) {
    int e = blockIdx.x * blockDim.x + threadIdx.x;
    if (e >= E) return;
    int src, dst;
    if (g_is64) {
        const long long* p = (const long long*)edges;
        src = (int)p[e]; dst = (int)p[E + e];
    } else {
        const int* p = (const int*)edges;
        src = p[e]; dst = p[E + e];
    }
    int pos = atomicAdd(&g_fill[dst], 1);
    g_esrc[pos] = src;
}

// fold weights: M1 = Wp1*Wt0, M2 = Wp2*Wt1, v = Wout*Wt2, bias
__global__ void matprep_kernel(const float* __restrict__ Wp,
                               const float* __restrict__ Wt,
                               const float* __restrict__ Wout,
                               const float* __restrict__ bout) {
    int t = blockIdx.x * blockDim.x + threadIdx.x;
    if (t >= DD * DD) return;
    int i = t >> 6, k = t & 63;
    float s1 = 0.f, s2 = 0.f;
#pragma unroll
    for (int m = 0; m < DD; m++) {
        s1 += Wp[1 * DD * DD + i * DD + m] * Wt[0 * DD * DD + m * DD + k];
        s2 += Wp[2 * DD * DD + i * DD + m] * Wt[1 * DD * DD + m * DD + k];
    }
    g_M1[t] = s1;
    g_M2[t] = s2;
    if (i == 0) {
        float sv = 0.f;
#pragma unroll
        for (int m = 0; m < DD; m++)
            sv += Wout[m] * Wt[2 * DD * DD + m * DD + k];
        g_v[k] = sv;
    }
    if (t == 0) g_bias = bout[0];
}

// ---------------- GEMM: out[64-row tile] = in @ M^T ----------------------
// Block: 256 threads, 64 rows x 64 cols tile, each thread a 4x4 micro-tile.
// Padded SMEM (stride 65) to avoid bank conflicts. No register spills.
__global__ void gemm_kernel(const float* __restrict__ x,
                            const float* __restrict__ M,
                            float* __restrict__ out, int N) {
    __shared__ float sx[DD][DD + 1];
    __shared__ float sM[DD][DD + 1];
    int t = threadIdx.x;
    int base = blockIdx.x * DD;

    // load tiles: 1024 float4 each, 4 per thread
#pragma unroll
    for (int i = 0; i < 4; i++) {
        int v = t + 256 * i;          // float4 index in [0,1024)
        int r = v >> 4;
        int c4 = (v & 15) * 4;
        // M tile (always full 64x64)
        float4 mv = *(const float4*)&M[r * DD + c4];
        sM[r][c4] = mv.x; sM[r][c4 + 1] = mv.y; sM[r][c4 + 2] = mv.z; sM[r][c4 + 3] = mv.w;
        // x tile (guard rows)
        float4 xv = make_float4(0.f, 0.f, 0.f, 0.f);
        if (base + r < N)
            xv = *(const float4*)&x[(size_t)(base + r) * DD + c4];
        sx[r][c4] = xv.x; sx[r][c4 + 1] = xv.y; sx[r][c4 + 2] = xv.z; sx[r][c4 + 3] = xv.w;
    }
    __syncthreads();

    int tc = (t & 15) * 4;    // col group base
    int tr = (t >> 4) * 4;    // row group base
    float acc[4][4];
#pragma unroll
    for (int i = 0; i < 4; i++)
#pragma unroll
        for (int j = 0; j < 4; j++) acc[i][j] = 0.f;

#pragma unroll 16
    for (int k = 0; k < DD; k++) {
        float a0 = sx[tr][k], a1 = sx[tr + 1][k], a2 = sx[tr + 2][k], a3 = sx[tr + 3][k];
        float b0 = sM[tc][k], b1 = sM[tc + 1][k], b2 = sM[tc + 2][k], b3 = sM[tc + 3][k];
        acc[0][0] += a0 * b0; acc[0][1] += a0 * b1; acc[0][2] += a0 * b2; acc[0][3] += a0 * b3;
        acc[1][0] += a1 * b0; acc[1][1] += a1 * b1; acc[1][2] += a1 * b2; acc[1][3] += a1 * b3;
        acc[2][0] += a2 * b0; acc[2][1] += a2 * b1; acc[2][2] += a2 * b2; acc[2][3] += a2 * b3;
        acc[3][0] += a3 * b0; acc[3][1] += a3 * b1; acc[3][2] += a3 * b2; acc[3][3] += a3 * b3;
    }

#pragma unroll
    for (int i = 0; i < 4; i++) {
        int row = base + tr + i;
        if (row < N) {
            float4 o = make_float4(acc[i][0], acc[i][1], acc[i][2], acc[i][3]);
            *(float4*)&out[(size_t)row * DD + tc] = o;
        }
    }
}

// ---------------- aggregation: warp per node, shfl-broadcast indices ------
// Lane owns columns 2*lane .. 2*lane+1 (float2, warp-coalesced 256B rows).
__device__ __forceinline__ void agg_core(const float* __restrict__ y,
                                         int beg, int end, int lane,
                                         float& mx, float& my) {
    mx = -INFINITY; my = -INFINITY;
    for (int base = beg; base < end; base += 32) {
        int cnt = end - base; if (cnt > 32) cnt = 32;
        int idx = (base + lane < end) ? g_esrc[base + lane] : 0;
        int k = 0;
        for (; k + 4 <= cnt; k += 4) {
            int j0 = __shfl_sync(0xffffffffu, idx, k);
            int j1 = __shfl_sync(0xffffffffu, idx, k + 1);
            int j2 = __shfl_sync(0xffffffffu, idx, k + 2);
            int j3 = __shfl_sync(0xffffffffu, idx, k + 3);
            float2 v0 = *(const float2*)&y[(size_t)j0 * DD + lane * 2];
            float2 v1 = *(const float2*)&y[(size_t)j1 * DD + lane * 2];
            float2 v2 = *(const float2*)&y[(size_t)j2 * DD + lane * 2];
            float2 v3 = *(const float2*)&y[(size_t)j3 * DD + lane * 2];
            mx = fmaxf(fmaxf(fmaxf(mx, v0.x), fmaxf(v1.x, v2.x)), v3.x);
            my = fmaxf(fmaxf(fmaxf(my, v0.y), fmaxf(v1.y, v2.y)), v3.y);
        }
        for (; k < cnt; k++) {
            int j0 = __shfl_sync(0xffffffffu, idx, k);
            float2 v0 = *(const float2*)&y[(size_t)j0 * DD + lane * 2];
            mx = fmaxf(mx, v0.x);
            my = fmaxf(my, v0.y);
        }
    }
}

__global__ void agg_kernel(const float* __restrict__ y,
                           float* __restrict__ out, int N) {
    int wid = (blockIdx.x * blockDim.x + threadIdx.x) >> 5;
    int lane = threadIdx.x & 31;
    if (wid >= N) return;
    int beg = g_rowptr[wid];
    int end = g_rowptr[wid + 1];
    float mx, my;
    agg_core(y, beg, end, lane, mx, my);
    float2 o;
    if (beg == end) {
        o.x = 0.f; o.y = 0.f;
    } else {
        float2 self = *(const float2*)&y[(size_t)wid * DD + lane * 2];
        o.x = mx - self.x;
        o.y = my - self.y;
    }
    *(float2*)&out[(size_t)wid * DD + lane * 2] = o;
}

// last layer: agg + dot with folded head vector + sigmoid, fused.
__global__ void agg_final_kernel(const float* __restrict__ y,
                                 float* __restrict__ out, int N) {
    int wid = (blockIdx.x * blockDim.x + threadIdx.x) >> 5;
    int lane = threadIdx.x & 31;
    if (wid >= N) return;
    int beg = g_rowptr[wid];
    int end = g_rowptr[wid + 1];
    float mx, my;
    agg_core(y, beg, end, lane, mx, my);
    float p = 0.f;
    if (beg != end) {
        float2 self = *(const float2*)&y[(size_t)wid * DD + lane * 2];
        float2 vv = *(const float2*)&g_v[lane * 2];
        p = (mx - self.x) * vv.x + (my - self.y) * vv.y;
    }
#pragma unroll
    for (int off = 16; off; off >>= 1)
        p += __shfl_xor_sync(0xffffffffu, p, off);
    if (lane == 0)
        out[wid] = 1.f / (1.f + expf(-(p + g_bias)));
}

extern "C" void kernel_launch(void* const* d_in, const int* in_sizes, int n_in,
                              void* d_out, int out_size) {
    const float* x     = (const float*)d_in[0];
    const void*  edges = d_in[1];
    const float* Wp    = (const float*)d_in[2];
    const float* Wt    = (const float*)d_in[3];
    const float* Wout  = (const float*)d_in[4];
    const float* bout  = (const float*)d_in[5];
    float* out = (float*)d_out;

    int N = in_sizes[0] / DD;
    int E = in_sizes[1] / 2;

    float *yp, *aggp, *m1p, *m2p;
    cudaGetSymbolAddress((void**)&yp, g_y);
    cudaGetSymbolAddress((void**)&aggp, g_agg);
    cudaGetSymbolAddress((void**)&m1p, g_M1);
    cudaGetSymbolAddress((void**)&m2p, g_M2);

    const int TB = 256;
    int ebl = (E + TB - 1) / TB;
    int nbl = (N + TB - 1) / TB;
    int wbl = ((N * 32) + TB - 1) / TB;   // warp-per-node grids
    int gbl = (N + DD - 1) / DD;          // 64-row GEMM tiles

    detect_kernel<<<1, 256>>>(edges);
    zero_kernel<<<nbl, TB>>>(N);
    hist_kernel<<<ebl, TB>>>(edges, E);
    scan_p1<<<SCAN_B, 256>>>(N);
    scan_p2<<<1, SCAN_B>>>(N);
    scan_p3<<<SCAN_B, 256>>>(N);
    scatter_kernel<<<ebl, TB>>>(edges, E);
    matprep_kernel<<<16, 256>>>(Wp, Wt, Wout, bout);

    // layer 0: y = x @ Wp0^T
    gemm_kernel<<<gbl, 256>>>(x, Wp, yp, N);
    agg_kernel<<<wbl, TB>>>(yp, aggp, N);
    // layer 1: y = agg @ (Wp1 Wt0)^T
    gemm_kernel<<<gbl, 256>>>(aggp, m1p, yp, N);
    agg_kernel<<<wbl, TB>>>(yp, aggp, N);
    // layer 2: y = agg @ (Wp2 Wt1)^T, head fused into aggregation
    gemm_kernel<<<gbl, 256>>>(aggp, m2p, yp, N);
    agg_final_kernel<<<wbl, TB>>>(yp, out, N);
}

// round 4
// speedup vs baseline: 3.5159x; 1.1746x over previous
#include <cuda_runtime.h>
#include <cuda_fp16.h>
#include <math.h>
#include <stdint.h>

#define NMAX 100000
#define EMAX 1600000
#define DD 64
#define SCAN_B 256        // scan grid blocks (256*512 = 131072 >= NMAX)

// ---------------- device scratch (no allocations allowed) ----------------
__device__ int    g_counts[NMAX];
__device__ int    g_fill[NMAX];
__device__ int    g_rowptr[NMAX + 1];
__device__ int    g_esrc[EMAX];
__device__ int    g_blocksums[SCAN_B];
__device__ int    g_blockoff[SCAN_B];
__device__ __half g_yh[(size_t)NMAX * DD];   // fp16 post-GEMM activations
__device__ float  g_agg[(size_t)NMAX * DD];  // fp32 aggregation output
__device__ float  g_M1[DD * DD];
__device__ float  g_M2[DD * DD];
__device__ float  g_v[DD];
__device__ float  g_bias;
__device__ int    g_is64;

// ---------------- dtype detection for edges (int64 vs int32) -------------
__global__ void detect_kernel(const void* __restrict__ edges) {
    __shared__ int nz;
    if (threadIdx.x == 0) nz = 0;
    __syncthreads();
    const int* w = (const int*)edges;
    int local = 0;
    for (int i = threadIdx.x; i < 2048; i += blockDim.x)
        if (w[2 * i + 1] != 0) local = 1;
    if (local) atomicOr(&nz, 1);
    __syncthreads();
    if (threadIdx.x == 0) g_is64 = (nz == 0) ? 1 : 0;
}

__global__ void zero_kernel(int n) {
    int i = blockIdx.x * blockDim.x + threadIdx.x;
    if (i < n) g_counts[i] = 0;
}

__global__ void hist_kernel(const void* __restrict__ edges, int E) {
    int e = blockIdx.x * blockDim.x + threadIdx.x;
    if (e >= E) return;
    int dst;
    if (g_is64) dst = (int)((const long long*)edges)[E + e];
    else        dst = ((const int*)edges)[E + e];
    atomicAdd(&g_counts[dst], 1);
}

// ---------------- 3-phase parallel exclusive scan -------------------------
__global__ void scan_p1(int N) {
    __shared__ int sm[256];
    int b = blockIdx.x, t = threadIdx.x;
    int base = b * 512 + t * 2;
    int s = 0;
    if (base < N)     s += g_counts[base];
    if (base + 1 < N) s += g_counts[base + 1];
    sm[t] = s;
    __syncthreads();
    for (int off = 128; off; off >>= 1) {
        if (t < off) sm[t] += sm[t + off];
        __syncthreads();
    }
    if (t == 0) g_blocksums[b] = sm[0];
}

__global__ void scan_p2(int N) {
    __shared__ int sm[SCAN_B];
    int t = threadIdx.x;
    int orig = g_blocksums[t];
    sm[t] = orig;
    __syncthreads();
    for (int off = 1; off < SCAN_B; off <<= 1) {
        int v = (t >= off) ? sm[t - off] : 0;
        __syncthreads();
        sm[t] += v;
        __syncthreads();
    }
    g_blockoff[t] = sm[t] - orig;
    if (t == SCAN_B - 1) g_rowptr[N] = sm[t];
}

__global__ void scan_p3(int N) {
    __shared__ int sm[256];
    int b = blockIdx.x, t = threadIdx.x;
    int base = b * 512 + t * 2;
    int c0 = (base < N) ? g_counts[base] : 0;
    int c1 = (base + 1 < N) ? g_counts[base + 1] : 0;
    int s = c0 + c1;
    sm[t] = s;
    __syncthreads();
    for (int off = 1; off < 256; off <<= 1) {
        int v = (t >= off) ? sm[t - off] : 0;
        __syncthreads();
        sm[t] += v;
        __syncthreads();
    }
    int pre = sm[t] - s + g_blockoff[b];
    if (base < N)     { g_rowptr[base] = pre;          g_fill[base] = pre; }
    if (base + 1 < N) { g_rowptr[base + 1] = pre + c0; g_fill[base + 1] = pre + c0; }
}

__global__ void scatter_kernel(const void* __restrict__ edges, int E) {
    int e = blockIdx.x * blockDim.x + threadIdx.x;
    if (e >= E) return;
    int src, dst;
    if (g_is64) {
        const long long* p = (const long long*)edges;
        src = (int)p[e]; dst = (int)p[E + e];
    } else {
        const int* p = (const int*)edges;
        src = p[e]; dst = p[E + e];
    }
    int pos = atomicAdd(&g_fill[dst], 1);
    g_esrc[pos] = src;
}

// fold weights: M1 = Wp1*Wt0, M2 = Wp2*Wt1, v = Wout*Wt2, bias
__global__ void matprep_kernel(const float* __restrict__ Wp,
                               const float* __restrict__ Wt,
                               const float* __restrict__ Wout,
                               const float* __restrict__ bout) {
    int t = blockIdx.x * blockDim.x + threadIdx.x;
    if (t >= DD * DD) return;
    int i = t >> 6, k = t & 63;
    float s1 = 0.f, s2 = 0.f;
#pragma unroll
    for (int m = 0; m < DD; m++) {
        s1 += Wp[1 * DD * DD + i * DD + m] * Wt[0 * DD * DD + m * DD + k];
        s2 += Wp[2 * DD * DD + i * DD + m] * Wt[1 * DD * DD + m * DD + k];
    }
    g_M1[t] = s1;
    g_M2[t] = s2;
    if (i == 0) {
        float sv = 0.f;
#pragma unroll
        for (int m = 0; m < DD; m++)
            sv += Wout[m] * Wt[2 * DD * DD + m * DD + k];
        g_v[k] = sv;
    }
    if (t == 0) g_bias = bout[0];
}

// ---------------- GEMM: yh[64-row tile] = half( in @ M^T ) ---------------
// 256 threads, 64x64 tile, 4x4 micro-tile per thread, fp32 accumulate,
// fp16 output (128B rows for the gather).
__global__ void gemm_kernel(const float* __restrict__ x,
                            const float* __restrict__ M,
                            __half* __restrict__ out, int N) {
    __shared__ float sx[DD][DD + 1];
    __shared__ float sM[DD][DD + 1];
    int t = threadIdx.x;
    int base = blockIdx.x * DD;

#pragma unroll
    for (int i = 0; i < 4; i++) {
        int v = t + 256 * i;
        int r = v >> 4;
        int c4 = (v & 15) * 4;
        float4 mv = *(const float4*)&M[r * DD + c4];
        sM[r][c4] = mv.x; sM[r][c4 + 1] = mv.y; sM[r][c4 + 2] = mv.z; sM[r][c4 + 3] = mv.w;
        float4 xv = make_float4(0.f, 0.f, 0.f, 0.f);
        if (base + r < N)
            xv = *(const float4*)&x[(size_t)(base + r) * DD + c4];
        sx[r][c4] = xv.x; sx[r][c4 + 1] = xv.y; sx[r][c4 + 2] = xv.z; sx[r][c4 + 3] = xv.w;
    }
    __syncthreads();

    int tc = (t & 15) * 4;
    int tr = (t >> 4) * 4;
    float acc[4][4];
#pragma unroll
    for (int i = 0; i < 4; i++)
#pragma unroll
        for (int j = 0; j < 4; j++) acc[i][j] = 0.f;

#pragma unroll 16
    for (int k = 0; k < DD; k++) {
        float a0 = sx[tr][k], a1 = sx[tr + 1][k], a2 = sx[tr + 2][k], a3 = sx[tr + 3][k];
        float b0 = sM[tc][k], b1 = sM[tc + 1][k], b2 = sM[tc + 2][k], b3 = sM[tc + 3][k];
        acc[0][0] += a0 * b0; acc[0][1] += a0 * b1; acc[0][2] += a0 * b2; acc[0][3] += a0 * b3;
        acc[1][0] += a1 * b0; acc[1][1] += a1 * b1; acc[1][2] += a1 * b2; acc[1][3] += a1 * b3;
        acc[2][0] += a2 * b0; acc[2][1] += a2 * b1; acc[2][2] += a2 * b2; acc[2][3] += a2 * b3;
        acc[3][0] += a3 * b0; acc[3][1] += a3 * b1; acc[3][2] += a3 * b2; acc[3][3] += a3 * b3;
    }

#pragma unroll
    for (int i = 0; i < 4; i++) {
        int row = base + tr + i;
        if (row < N) {
            __half2 h0 = __floats2half2_rn(acc[i][0], acc[i][1]);
            __half2 h1 = __floats2half2_rn(acc[i][2], acc[i][3]);
            uint2 pack;
            pack.x = *(const unsigned*)&h0;
            pack.y = *(const unsigned*)&h1;
            *(uint2*)&out[(size_t)row * DD + tc] = pack;
        }
    }
}

// ---------------- aggregation core (fp16 gather) --------------------------
// Warp per node. Half-warp per edge: lane = half*16 + q; lane owns columns
// q*4..q*4+3 via one 8B load (row = 128B = one L2 line). Tail edges are
// processed redundantly by both halves (max is idempotent). After the loop,
// fold across halves; every lane holds the max for its q's 4 columns.
__device__ __forceinline__ void agg_core_h(const __half* __restrict__ yh,
                                           int beg, int end, int lane,
                                           __half2& m01, __half2& m23) {
    const __half2 ninf = __float2half2_rn(-INFINITY);
    m01 = ninf; m23 = ninf;
    int half_id = lane >> 4;
    int q = lane & 15;
    for (int b = beg; b < end; b += 32) {
        int cnt = end - b; if (cnt > 32) cnt = 32;
        int idx = (b + lane < end) ? g_esrc[b + lane] : 0;
        int p = 0;
        for (; p + 4 <= cnt; p += 4) {       // 2 edges per half-warp, MLP=2
            int jA = __shfl_sync(0xffffffffu, idx, p + half_id);
            int jB = __shfl_sync(0xffffffffu, idx, p + 2 + half_id);
            uint2 a = *(const uint2*)&yh[(size_t)jA * DD + q * 4];
            uint2 c = *(const uint2*)&yh[(size_t)jB * DD + q * 4];
            m01 = __hmax2(m01, __hmax2(*(__half2*)&a.x, *(__half2*)&c.x));
            m23 = __hmax2(m23, __hmax2(*(__half2*)&a.y, *(__half2*)&c.y));
        }
        for (; p < cnt; p++) {               // tail: both halves duplicate
            int j = __shfl_sync(0xffffffffu, idx, p);
            uint2 a = *(const uint2*)&yh[(size_t)j * DD + q * 4];
            m01 = __hmax2(m01, *(__half2*)&a.x);
            m23 = __hmax2(m23, *(__half2*)&a.y);
        }
    }
    // fold across half-warps
    unsigned u01 = *(unsigned*)&m01, u23 = *(unsigned*)&m23;
    unsigned o01 = __shfl_xor_sync(0xffffffffu, u01, 16);
    unsigned o23 = __shfl_xor_sync(0xffffffffu, u23, 16);
    m01 = __hmax2(m01, *(__half2*)&o01);
    m23 = __hmax2(m23, *(__half2*)&o23);
}

// agg[i] = max_{src} yh[src] - yh[i]  (fp32 output; 0 for isolated nodes)
__global__ void agg_kernel(const __half* __restrict__ yh,
                           float* __restrict__ out, int N) {
    int wid = (blockIdx.x * blockDim.x + threadIdx.x) >> 5;
    int lane = threadIdx.x & 31;
    if (wid >= N) return;
    int beg = g_rowptr[wid];
    int end = g_rowptr[wid + 1];
    __half2 m01, m23;
    agg_core_h(yh, beg, end, lane, m01, m23);
    if (lane < 16) {
        int q = lane;
        float4 o;
        if (beg == end) {
            o = make_float4(0.f, 0.f, 0.f, 0.f);
        } else {
            uint2 s = *(const uint2*)&yh[(size_t)wid * DD + q * 4];
            float2 f01 = __half22float2(m01);
            float2 f23 = __half22float2(m23);
            float2 s01 = __half22float2(*(__half2*)&s.x);
            float2 s23 = __half22float2(*(__half2*)&s.y);
            o.x = f01.x - s01.x; o.y = f01.y - s01.y;
            o.z = f23.x - s23.x; o.w = f23.y - s23.y;
        }
        *(float4*)&out[(size_t)wid * DD + q * 4] = o;
    }
}

// last layer: agg + dot with folded head vector + sigmoid, fused.
__global__ void agg_final_kernel(const __half* __restrict__ yh,
                                 float* __restrict__ out, int N) {
    int wid = (blockIdx.x * blockDim.x + threadIdx.x) >> 5;
    int lane = threadIdx.x & 31;
    if (wid >= N) return;
    int beg = g_rowptr[wid];
    int end = g_rowptr[wid + 1];
    __half2 m01, m23;
    agg_core_h(yh, beg, end, lane, m01, m23);
    int q = lane & 15;
    float p = 0.f;
    if (beg != end) {
        uint2 s = *(const uint2*)&yh[(size_t)wid * DD + q * 4];
        float2 f01 = __half22float2(m01);
        float2 f23 = __half22float2(m23);
        float2 s01 = __half22float2(*(__half2*)&s.x);
        float2 s23 = __half22float2(*(__half2*)&s.y);
        float4 vv = *(const float4*)&g_v[q * 4];
        p = (f01.x - s01.x) * vv.x + (f01.y - s01.y) * vv.y
          + (f23.x - s23.x) * vv.z + (f23.y - s23.y) * vv.w;
    }
    // lanes 16-31 mirror lanes 0-15; reduce within each half
#pragma unroll
    for (int off = 8; off; off >>= 1)
        p += __shfl_xor_sync(0xffffffffu, p, off);
    if (lane == 0)
        out[wid] = 1.f / (1.f + expf(-(p + g_bias)));
}

extern "C" void kernel_launch(void* const* d_in, const int* in_sizes, int n_in,
                              void* d_out, int out_size) {
    const float* x     = (const float*)d_in[0];
    const void*  edges = d_in[1];
    const float* Wp    = (const float*)d_in[2];
    const float* Wt    = (const float*)d_in[3];
    const float* Wout  = (const float*)d_in[4];
    const float* bout  = (const float*)d_in[5];
    float* out = (float*)d_out;

    int N = in_sizes[0] / DD;
    int E = in_sizes[1] / 2;

    __half* yhp;
    float *aggp, *m1p, *m2p;
    cudaGetSymbolAddress((void**)&yhp, g_yh);
    cudaGetSymbolAddress((void**)&aggp, g_agg);
    cudaGetSymbolAddress((void**)&m1p, g_M1);
    cudaGetSymbolAddress((void**)&m2p, g_M2);

    const int TB = 256;
    int ebl = (E + TB - 1) / TB;
    int nbl = (N + TB - 1) / TB;
    int wbl = ((N * 32) + TB - 1) / TB;   // warp-per-node grids
    int gbl = (N + DD - 1) / DD;          // 64-row GEMM tiles

    detect_kernel<<<1, 256>>>(edges);
    zero_kernel<<<nbl, TB>>>(N);
    hist_kernel<<<ebl, TB>>>(edges, E);
    scan_p1<<<SCAN_B, 256>>>(N);
    scan_p2<<<1, SCAN_B>>>(N);
    scan_p3<<<SCAN_B, 256>>>(N);
    scatter_kernel<<<ebl, TB>>>(edges, E);
    matprep_kernel<<<16, 256>>>(Wp, Wt, Wout, bout);

    // layer 0: yh = half(x @ Wp0^T)
    gemm_kernel<<<gbl, 256>>>(x, Wp, yhp, N);
    agg_kernel<<<wbl, TB>>>(yhp, aggp, N);
    // layer 1: yh = half(agg @ (Wp1 Wt0)^T)
    gemm_kernel<<<gbl, 256>>>(aggp, m1p, yhp, N);
    agg_kernel<<<wbl, TB>>>(yhp, aggp, N);
    // layer 2: yh = half(agg @ (Wp2 Wt1)^T), head fused into aggregation
    gemm_kernel<<<gbl, 256>>>(aggp, m2p, yhp, N);
    agg_final_kernel<<<wbl, TB>>>(yhp, out, N);
}